// round 15
// baseline (speedup 1.0000x reference)
#include <cuda_runtime.h>
#include <cuda_bf16.h>
#include <cstdint>

#define BB 64
#define CC 384
#define C2 192
#define HW 1024
#define CR 24
#define P24K 24576
#define NTOK 65536
#define HID 1536
#define KPAD 40
#define NS 4
#define GEMM_SMEM (NS*128*KPAD*2*2)   // 81920 B

__device__ float          g_p[BB*CC];
__device__ float          g_h[BB*CR];
__device__ float2         g_stats[BB];
__device__ float          g_params[BB*P24K];         // RAW dyn params
__device__ __nv_bfloat16  g_y[(size_t)BB*CC*HW];
__device__ __nv_bfloat16  g_aln[(size_t)NTOK*CC];
__device__ __nv_bfloat16  g_hid[(size_t)NTOK*HID];
__device__ __nv_bfloat16  g_w1b[HID*CC];
__device__ __nv_bfloat16  g_w2b[CC*HID];

__device__ __forceinline__ unsigned smem_u32(const void* p){return (unsigned)__cvta_generic_to_shared(p);}
__device__ __forceinline__ void cp16(void* s,const void* g){
    asm volatile("cp.async.cg.shared.global [%0], [%1], 16;\n"::"r"(smem_u32(s)),"l"(g));}
__device__ __forceinline__ void cp_commit(){asm volatile("cp.async.commit_group;\n");}
template<int N> __device__ __forceinline__ void cp_wait(){asm volatile("cp.async.wait_group %0;\n"::"n"(N));}
__device__ __forceinline__ void ldm_x4(unsigned addr,unsigned&r0,unsigned&r1,unsigned&r2,unsigned&r3){
    asm volatile("ldmatrix.sync.aligned.m8n8.x4.shared.b16 {%0,%1,%2,%3}, [%4];\n"
                 :"=r"(r0),"=r"(r1),"=r"(r2),"=r"(r3):"r"(addr));}
__device__ __forceinline__ void mma16816(float* c,unsigned a0,unsigned a1,unsigned a2,unsigned a3,
                                         unsigned b0,unsigned b1){
    asm volatile(
        "mma.sync.aligned.m16n8k16.row.col.f32.bf16.bf16.f32 "
        "{%0,%1,%2,%3},{%4,%5,%6,%7},{%8,%9},{%0,%1,%2,%3};\n"
        :"+f"(c[0]),"+f"(c[1]),"+f"(c[2]),"+f"(c[3])
        :"r"(a0),"r"(a1),"r"(a2),"r"(a3),"r"(b0),"r"(b1));}
__device__ __forceinline__ float gelu_t(float v){
    float u=v*(0.7978845608028654f+0.0356774081f*v*v);
    float t; asm("tanh.approx.f32 %0, %1;":"=f"(t):"f"(u));
    return 0.5f*v*(1.0f+t);}

// ---------------- k0: weights -> bf16 ----------------
__global__ void __launch_bounds__(256) cvt_w_kernel(const float* __restrict__ w1,
                                                    const float* __restrict__ w2){
    int i=blockIdx.x*256+threadIdx.x;
    if(i<HID*CC){
        g_w1b[i]=__float2bfloat16(w1[i]);
        g_w2b[i]=__float2bfloat16(w2[i]);
    }
}

// ---------------- k1: spatial mean pool ----------------
__global__ void __launch_bounds__(256) pool_kernel(const float* __restrict__ x){
    const float4* xr=reinterpret_cast<const float4*>(x+(size_t)blockIdx.x*HW);
    float4 v=xr[threadIdx.x];
    float s=v.x+v.y+v.z+v.w;
    #pragma unroll
    for(int o=16;o>0;o>>=1) s+=__shfl_down_sync(0xffffffffu,s,o);
    __shared__ float ws[8];
    if((threadIdx.x&31)==0) ws[threadIdx.x>>5]=s;
    __syncthreads();
    if(threadIdx.x<8){
        float t=ws[threadIdx.x];
        #pragma unroll
        for(int o=4;o>0;o>>=1) t+=__shfl_down_sync(0xffu,t,o);
        if(threadIdx.x==0) g_p[blockIdx.x]=t*(1.0f/1024.0f);
    }
}

// ---------------- k2a: h = relu(bn(p @ kp_w1^T)) ----------------
__global__ void __launch_bounds__(32) params_h_kernel(
    const float* __restrict__ kp_w1,const float* __restrict__ bng,const float* __restrict__ bnb,
    const float* __restrict__ bnm,const float* __restrict__ bnv){
    int b=blockIdx.x,tid=threadIdx.x;
    if(tid<CR){
        const float* p=g_p+b*CC;
        const float* wr=kp_w1+tid*CC;
        float s=0.f;
        #pragma unroll 8
        for(int c=0;c<CC;++c) s+=p[c]*wr[c];
        s=(s-bnm[tid])*rsqrtf(bnv[tid]+1e-5f)*bng[tid]+bnb[tid];
        g_h[b*CR+tid]=fmaxf(s,0.0f);
    }
}

// ---------------- k2b: raw params GEMM, grid (96,2): 256 rows x 32 batches ----------
#define WSP 25
__global__ void __launch_bounds__(256) params_gemm_kernel(
    const float* __restrict__ kp_w2,const float* __restrict__ kp_b2){
    __shared__ float hs[32*CR];
    __shared__ float ws[256*WSP];
    int tid=threadIdx.x;
    int base=blockIdx.x*256;
    int b0=blockIdx.y*32;
    for(int i=tid;i<32*CR;i+=256) hs[i]=g_h[b0*CR+i];
    const float* wsrc=kp_w2+(size_t)base*CR;
    for(int i=tid;i<256*CR;i+=256){
        int r=i/CR,c=i-r*CR;
        ws[r*WSP+c]=wsrc[i];
    }
    __syncthreads();
    float w[CR];
    #pragma unroll
    for(int j=0;j<CR;++j) w[j]=ws[tid*WSP+j];
    float bi=__ldg(&kp_b2[base+tid]);
    float* gp=g_params+(size_t)b0*P24K+base+tid;
    #pragma unroll 4
    for(int b=0;b<32;++b){
        const float* hb=hs+b*CR;
        float s=bi;
        #pragma unroll
        for(int j=0;j<CR;++j) s+=hb[j]*w[j];
        gp[(size_t)b*P24K]=s;
    }
}

// ---------------- k2c: per-batch stats (u, inv_sigma) ----------------
__global__ void __launch_bounds__(256) params_stats_kernel(){
    int b=blockIdx.x,tid=threadIdx.x;
    const float4* gp=reinterpret_cast<const float4*>(g_params+(size_t)b*P24K);
    float s1=0.f,s2=0.f;
    #pragma unroll
    for(int it=0;it<24;++it){
        float4 v=gp[tid+it*256];
        s1+=v.x+v.y+v.z+v.w;
        s2+=v.x*v.x+v.y*v.y+v.z*v.z+v.w*v.w;
    }
    #pragma unroll
    for(int o=16;o>0;o>>=1){
        s1+=__shfl_down_sync(0xffffffffu,s1,o);
        s2+=__shfl_down_sync(0xffffffffu,s2,o);
    }
    __shared__ float r1[8],r2[8];
    if((tid&31)==0){ r1[tid>>5]=s1; r2[tid>>5]=s2; }
    __syncthreads();
    if(tid==0){
        float a=0.f,q=0.f;
        #pragma unroll
        for(int g=0;g<8;++g){a+=r1[g]; q+=r2[g];}
        float u=a*(1.0f/P24K);
        float var=q*(1.0f/P24K)-u*u;
        g_stats[b]=make_float2(u,rsqrtf(var+1e-12f));
    }
}

// ---------------- k3: circular conv + PE(featnorm inline) + bias -> bf16 y ------------
__global__ void __launch_bounds__(256) conv_kernel(const float* __restrict__ x,
                                                   const float* __restrict__ bias,
                                                   const float* __restrict__ fn_std,
                                                   const float* __restrict__ fn_mean){
    __shared__ float tile[32*33];
    __shared__ float pe_s[32];
    int tid=threadIdx.x,bc=blockIdx.x;
    int b=bc/CC,ch=bc%CC;
    const float* pb=g_params+(size_t)b*P24K;
    float2 st=g_stats[b];
    float u=st.x,inv=st.y;
    bool modeH=(ch<C2);
    int kidx=modeH?((2*C2+ch)*32):((3*C2+(ch-C2))*32);
    int pidx=modeH?(ch*32):((C2+(ch-C2))*32);
    int lane=tid&31,h0=tid>>5;
    if(tid<32){
        float raw=pb[pidx+tid];
        pe_s[tid]=(raw-u)*inv*__ldg(&fn_std[pidx+tid])+__ldg(&fn_mean[pidx+tid]);
    }
    float kraw=__ldg(&pb[kidx+lane]);
    float kv=(kraw-u)*inv*__ldg(&fn_std[kidx+lane])+__ldg(&fn_mean[kidx+lane]);
    __syncthreads();
    const float* xb=x+(size_t)bc*HW;
    #pragma unroll
    for(int r=0;r<4;++r){
        int idx=tid+r*256,g=idx>>5,w=idx&31;
        tile[g*33+w]=xb[idx]+(modeH?pe_s[g]:pe_s[w]);
    }
    __syncthreads();
    float bi=__ldg(&bias[ch]);
    float a0=0.f,a1=0.f,a2=0.f,a3=0.f,krot[32];
    if(modeH){
        #pragma unroll
        for(int g=0;g<32;++g) krot[g]=__shfl_sync(0xffffffffu,kv,(g-h0)&31);
        #pragma unroll
        for(int g=0;g<32;++g){
            float tv=tile[g*33+lane];
            a0+=krot[g]*tv;           a1+=krot[(g-8)&31]*tv;
            a2+=krot[(g-16)&31]*tv;   a3+=krot[(g-24)&31]*tv;
        }
    }else{
        #pragma unroll
        for(int v=0;v<32;++v) krot[v]=__shfl_sync(0xffffffffu,kv,(v-lane)&31);
        #pragma unroll
        for(int v=0;v<32;++v){
            float kvv=krot[v];
            a0+=kvv*tile[h0*33+v];        a1+=kvv*tile[(h0+8)*33+v];
            a2+=kvv*tile[(h0+16)*33+v];   a3+=kvv*tile[(h0+24)*33+v];
        }
    }
    __nv_bfloat16* yo=g_y+(size_t)bc*HW;
    yo[h0*32+lane]      =__float2bfloat16(a0+bi);
    yo[(h0+8)*32+lane]  =__float2bfloat16(a1+bi);
    yo[(h0+16)*32+lane] =__float2bfloat16(a2+bi);
    yo[(h0+24)*32+lane] =__float2bfloat16(a3+bi);
}

// ---------------- k4: channel LN (bf16 in) -> token-major bf16 ----------------
__global__ void __launch_bounds__(256) ln_kernel(const float* __restrict__ ln_w,
                                                 const float* __restrict__ ln_b){
    int tid=threadIdx.x;
    int tok0=blockIdx.x*32;
    int b=tok0>>10,hw0=tok0&1023;
    int j=tid&31,cg=tid>>5;
    const __nv_bfloat16* yb=g_y+(size_t)b*CC*HW+hw0+j;
    float vals[48],s1=0.f,s2=0.f;
    #pragma unroll
    for(int i=0;i<48;++i){
        int c=cg+i*8;
        float v=__bfloat162float(yb[(size_t)c*HW]);
        vals[i]=v; s1+=v; s2+=v*v;
    }
    __shared__ float rs1[8][32],rs2[8][32],muS[32],rstdS[32];
    rs1[cg][j]=s1; rs2[cg][j]=s2;
    __syncthreads();
    if(tid<32){
        float a=0.f,q=0.f;
        #pragma unroll
        for(int g=0;g<8;++g){a+=rs1[g][tid]; q+=rs2[g][tid];}
        float mu=a*(1.0f/CC);
        float var=q*(1.0f/CC)-mu*mu;
        muS[tid]=mu; rstdS[tid]=rsqrtf(var+1e-6f);
    }
    __syncthreads();
    __shared__ __nv_bfloat16 smo[32*386];
    float mu=muS[j],rsd=rstdS[j];
    #pragma unroll
    for(int i=0;i<48;++i){
        int c=cg+i*8;
        float t=(vals[i]-mu)*rsd*ln_w[c]+ln_b[c];
        smo[j*386+c]=__float2bfloat16(t);
    }
    __syncthreads();
    __nv_bfloat16* ao=g_aln+(size_t)tok0*CC;
    for(int idx=tid;idx<32*CC;idx+=256){
        int jj=idx/CC,ccx=idx-jj*CC;
        ao[idx]=smo[jj*386+ccx];
    }
}

// ---------------- bf16 GEMM mainloop: 128x128xK, 4 warps @ 64x64, NS=4 ----------------
template<int KDIM>
__device__ __forceinline__ void gemm_tile(const __nv_bfloat16* __restrict__ A,
                                          const __nv_bfloat16* __restrict__ W,
                                          int mBase,int nBase,float acc[4][8][4],
                                          __nv_bfloat16* As,__nv_bfloat16* Ws){
    const int tid=threadIdx.x;
    const int lane=tid&31,warp=tid>>5;
    const int wm=(warp&1)*64,wn=(warp>>1)*64;
    constexpr int KT=KDIM/32;

    auto load_stage=[&](int s,int kt){
        int k0=kt*32;
        __nv_bfloat16* as=As+s*(128*KPAD);
        __nv_bfloat16* ws=Ws+s*(128*KPAD);
        #pragma unroll
        for(int i=tid;i<512;i+=128){
            int row=i>>2,seg=(i&3)*8;
            cp16(as+row*KPAD+seg,A+(size_t)(mBase+row)*KDIM+k0+seg);
            cp16(ws+row*KPAD+seg,W+(size_t)(nBase+row)*KDIM+k0+seg);
        }
        cp_commit();
    };

    load_stage(0,0); load_stage(1,1); load_stage(2,2);

    for(int kt=0;kt<KT;++kt){
        int s=kt&(NS-1);
        cp_wait<NS-2>();
        __syncthreads();
        if(kt+NS-1<KT) load_stage((kt+NS-1)&(NS-1),kt+NS-1);
        else           cp_commit();
        __nv_bfloat16* as=As+s*(128*KPAD);
        __nv_bfloat16* ws=Ws+s*(128*KPAD);
        #pragma unroll
        for(int kk=0;kk<2;++kk){
            unsigned a[4][4],bq[4][4];
            #pragma unroll
            for(int mi=0;mi<4;++mi)
                ldm_x4(smem_u32(as+(wm+mi*16+(lane&15))*KPAD+kk*16+(lane>>4)*8),
                       a[mi][0],a[mi][1],a[mi][2],a[mi][3]);
            #pragma unroll
            for(int nq=0;nq<4;++nq)
                ldm_x4(smem_u32(ws+(wn+nq*16+(lane&15))*KPAD+kk*16+(lane>>4)*8),
                       bq[nq][0],bq[nq][1],bq[nq][2],bq[nq][3]);
            #pragma unroll
            for(int mi=0;mi<4;++mi)
                #pragma unroll
                for(int ni=0;ni<8;++ni){
                    int nq=ni>>1,hp=ni&1;
                    mma16816(acc[mi][ni],a[mi][0],a[mi][1],a[mi][2],a[mi][3],
                             bq[nq][hp],bq[nq][2+hp]);
                }
        }
    }
}

// ---------------- k5: GEMM1 + bias + GELU(tanh) -> g_hid ----------------
__global__ void __launch_bounds__(128) gemm1_kernel(const float* __restrict__ b1){
    extern __shared__ __align__(16) __nv_bfloat16 sm[];
    __nv_bfloat16* As=sm;
    __nv_bfloat16* Ws=sm+NS*128*KPAD;
    float acc[4][8][4];
    #pragma unroll
    for(int i=0;i<4;++i)
        #pragma unroll
        for(int j=0;j<8;++j)
            #pragma unroll
            for(int k=0;k<4;++k) acc[i][j][k]=0.f;

    int mBase=blockIdx.y*128,nBase=blockIdx.x*128;
    gemm_tile<CC>(g_aln,g_w1b,mBase,nBase,acc,As,Ws);

    int lane=threadIdx.x&31,warp=threadIdx.x>>5;
    int wm=mBase+(warp&1)*64,wn=nBase+(warp>>1)*64;
    #pragma unroll
    for(int mi=0;mi<4;++mi)
        #pragma unroll
        for(int ni=0;ni<8;++ni){
            int n=wn+ni*8+(lane&3)*2;
            float bn0=__ldg(&b1[n]),bn1=__ldg(&b1[n+1]);
            int m=wm+mi*16+(lane>>2);
            float c0=gelu_t(acc[mi][ni][0]+bn0);
            float c1=gelu_t(acc[mi][ni][1]+bn1);
            float c2=gelu_t(acc[mi][ni][2]+bn0);
            float c3=gelu_t(acc[mi][ni][3]+bn1);
            *reinterpret_cast<__nv_bfloat162*>(&g_hid[(size_t)m*HID+n])=__floats2bfloat162_rn(c0,c1);
            *reinterpret_cast<__nv_bfloat162*>(&g_hid[(size_t)(m+8)*HID+n])=__floats2bfloat162_rn(c2,c3);
        }
}

// ---------------- k6: GEMM2 + bias + gamma*t + residual -> out ----------------
__global__ void __launch_bounds__(128) gemm2_kernel(const float* __restrict__ x,
                                                    const float* __restrict__ b2,
                                                    const float* __restrict__ gamma,
                                                    float* __restrict__ out){
    extern __shared__ __align__(16) __nv_bfloat16 sm[];
    __nv_bfloat16* As=sm;
    __nv_bfloat16* Ws=sm+NS*128*KPAD;
    float acc[4][8][4];
    #pragma unroll
    for(int i=0;i<4;++i)
        #pragma unroll
        for(int j=0;j<8;++j)
            #pragma unroll
            for(int k=0;k<4;++k) acc[i][j][k]=0.f;

    int mBase=blockIdx.y*128,nBase=blockIdx.x*128;
    gemm_tile<HID>(g_hid,g_w2b,mBase,nBase,acc,As,Ws);

    int lane=threadIdx.x&31,warp=threadIdx.x>>5;
    int wm=mBase+(warp&1)*64,wn=nBase+(warp>>1)*64;
    #pragma unroll
    for(int mi=0;mi<4;++mi)
        #pragma unroll
        for(int ni=0;ni<8;++ni){
            int n=wn+ni*8+(lane&3)*2;
            float bb0=__ldg(&b2[n]),bb1=__ldg(&b2[n+1]);
            float gm0=__ldg(&gamma[n]),gm1=__ldg(&gamma[n+1]);
            int m0=wm+mi*16+(lane>>2);
            #pragma unroll
            for(int half=0;half<2;++half){
                int m=m0+half*8;
                float v0=acc[mi][ni][half*2+0]+bb0;
                float v1=acc[mi][ni][half*2+1]+bb1;
                int b=m>>10,hw=m&1023;
                size_t i0=((size_t)(b*CC+n)<<10)+hw;
                out[i0]     =x[i0]     +gm0*v0;
                out[i0+1024]=x[i0+1024]+gm1*v1;
            }
        }
}

// ---------------- launch ----------------
extern "C" void kernel_launch(void* const* d_in, const int* in_sizes, int n_in,
                              void* d_out, int out_size) {
    const float* x       = (const float*)d_in[0];
    const float* kp_w1   = (const float*)d_in[1];
    const float* bng     = (const float*)d_in[2];
    const float* bnb     = (const float*)d_in[3];
    const float* bnm     = (const float*)d_in[4];
    const float* bnv     = (const float*)d_in[5];
    const float* kp_w2   = (const float*)d_in[6];
    const float* kp_b2   = (const float*)d_in[7];
    const float* fn_std  = (const float*)d_in[8];
    const float* fn_mean = (const float*)d_in[9];
    const float* bias    = (const float*)d_in[10];
    const float* ln_w    = (const float*)d_in[11];
    const float* ln_b    = (const float*)d_in[12];
    const float* w1      = (const float*)d_in[13];
    const float* b1      = (const float*)d_in[14];
    const float* w2      = (const float*)d_in[15];
    const float* b2      = (const float*)d_in[16];
    const float* gamma   = (const float*)d_in[17];
    float* out = (float*)d_out;

    static bool attr_set=false;
    if(!attr_set){
        cudaFuncSetAttribute(gemm1_kernel,cudaFuncAttributeMaxDynamicSharedMemorySize,GEMM_SMEM);
        cudaFuncSetAttribute(gemm2_kernel,cudaFuncAttributeMaxDynamicSharedMemorySize,GEMM_SMEM);
        attr_set=true;
    }

    cvt_w_kernel<<<(HID*CC+255)/256,256>>>(w1,w2);
    pool_kernel<<<BB*CC,256>>>(x);
    params_h_kernel<<<BB,32>>>(kp_w1,bng,bnb,bnm,bnv);
    params_gemm_kernel<<<dim3(P24K/256,2),256>>>(kp_w2,kp_b2);
    params_stats_kernel<<<BB,256>>>();
    conv_kernel<<<BB*CC,256>>>(x,bias,fn_std,fn_mean);
    ln_kernel<<<NTOK/32,256>>>(ln_w,ln_b);
    gemm1_kernel<<<dim3(HID/128,NTOK/128),128,GEMM_SMEM>>>(b1);
    gemm2_kernel<<<dim3(CC/128,NTOK/128),128,GEMM_SMEM>>>(x,b2,gamma,out);
}

// round 16
// speedup vs baseline: 1.0181x; 1.0181x over previous
#include <cuda_runtime.h>
#include <cuda_bf16.h>
#include <cstdint>

#define BB 64
#define CC 384
#define C2 192
#define HW 1024
#define CR 24
#define P24K 24576
#define NTOK 65536
#define HID 1536
#define KPAD 40
#define NS 4
#define GEMM_SMEM (NS*128*KPAD*2*2)   // 81920 B

__device__ float          g_p[BB*CC];
__device__ float          g_h[BB*CR];
__device__ float2         g_stats[BB];
__device__ float          g_params[BB*P24K];         // RAW dyn params
__device__ __nv_bfloat16  g_y[(size_t)BB*CC*HW];
__device__ __nv_bfloat16  g_aln[(size_t)NTOK*CC];
__device__ __nv_bfloat16  g_hid[(size_t)NTOK*HID];
__device__ __nv_bfloat16  g_w1b[HID*CC];
__device__ __nv_bfloat16  g_w2b[CC*HID];

__device__ __forceinline__ unsigned smem_u32(const void* p){return (unsigned)__cvta_generic_to_shared(p);}
__device__ __forceinline__ void cp16(void* s,const void* g){
    asm volatile("cp.async.cg.shared.global [%0], [%1], 16;\n"::"r"(smem_u32(s)),"l"(g));}
__device__ __forceinline__ void cp_commit(){asm volatile("cp.async.commit_group;\n");}
template<int N> __device__ __forceinline__ void cp_wait(){asm volatile("cp.async.wait_group %0;\n"::"n"(N));}
__device__ __forceinline__ void ldm_x4(unsigned addr,unsigned&r0,unsigned&r1,unsigned&r2,unsigned&r3){
    asm volatile("ldmatrix.sync.aligned.m8n8.x4.shared.b16 {%0,%1,%2,%3}, [%4];\n"
                 :"=r"(r0),"=r"(r1),"=r"(r2),"=r"(r3):"r"(addr));}
__device__ __forceinline__ void mma16816(float* c,unsigned a0,unsigned a1,unsigned a2,unsigned a3,
                                         unsigned b0,unsigned b1){
    asm volatile(
        "mma.sync.aligned.m16n8k16.row.col.f32.bf16.bf16.f32 "
        "{%0,%1,%2,%3},{%4,%5,%6,%7},{%8,%9},{%0,%1,%2,%3};\n"
        :"+f"(c[0]),"+f"(c[1]),"+f"(c[2]),"+f"(c[3])
        :"r"(a0),"r"(a1),"r"(a2),"r"(a3),"r"(b0),"r"(b1));}
__device__ __forceinline__ float gelu_t(float v){
    float u=v*(0.7978845608028654f+0.0356774081f*v*v);
    float t; asm("tanh.approx.f32 %0, %1;":"=f"(t):"f"(u));
    return 0.5f*v*(1.0f+t);}

// ---------------- k0: weights -> bf16 ----------------
__global__ void __launch_bounds__(256) cvt_w_kernel(const float* __restrict__ w1,
                                                    const float* __restrict__ w2){
    int i=blockIdx.x*256+threadIdx.x;
    if(i<HID*CC){
        g_w1b[i]=__float2bfloat16(w1[i]);
        g_w2b[i]=__float2bfloat16(w2[i]);
    }
}

// ---------------- k1: spatial mean pool ----------------
__global__ void __launch_bounds__(256) pool_kernel(const float* __restrict__ x){
    const float4* xr=reinterpret_cast<const float4*>(x+(size_t)blockIdx.x*HW);
    float4 v=xr[threadIdx.x];
    float s=v.x+v.y+v.z+v.w;
    #pragma unroll
    for(int o=16;o>0;o>>=1) s+=__shfl_down_sync(0xffffffffu,s,o);
    __shared__ float ws[8];
    if((threadIdx.x&31)==0) ws[threadIdx.x>>5]=s;
    __syncthreads();
    if(threadIdx.x<8){
        float t=ws[threadIdx.x];
        #pragma unroll
        for(int o=4;o>0;o>>=1) t+=__shfl_down_sync(0xffu,t,o);
        if(threadIdx.x==0) g_p[blockIdx.x]=t*(1.0f/1024.0f);
    }
}

// ---------------- k2a: h = relu(bn(p @ kp_w1^T)) ----------------
__global__ void __launch_bounds__(32) params_h_kernel(
    const float* __restrict__ kp_w1,const float* __restrict__ bng,const float* __restrict__ bnb,
    const float* __restrict__ bnm,const float* __restrict__ bnv){
    int b=blockIdx.x,tid=threadIdx.x;
    if(tid<CR){
        const float* p=g_p+b*CC;
        const float* wr=kp_w1+tid*CC;
        float s=0.f;
        #pragma unroll 8
        for(int c=0;c<CC;++c) s+=p[c]*wr[c];
        s=(s-bnm[tid])*rsqrtf(bnv[tid]+1e-5f)*bng[tid]+bnb[tid];
        g_h[b*CR+tid]=fmaxf(s,0.0f);
    }
}

// ---------------- k2b: raw params GEMM, grid (96,4): 256 rows x 16 batches ----------
#define WSP 25
__global__ void __launch_bounds__(256) params_gemm_kernel(
    const float* __restrict__ kp_w2,const float* __restrict__ kp_b2){
    __shared__ float hs[16*CR];
    __shared__ float ws[256*WSP];
    int tid=threadIdx.x;
    int base=blockIdx.x*256;
    int b0=blockIdx.y*16;
    for(int i=tid;i<16*CR;i+=256) hs[i]=g_h[b0*CR+i];
    const float* wsrc=kp_w2+(size_t)base*CR;
    for(int i=tid;i<256*CR;i+=256){
        int r=i/CR,c=i-r*CR;
        ws[r*WSP+c]=wsrc[i];
    }
    __syncthreads();
    float w[CR];
    #pragma unroll
    for(int j=0;j<CR;++j) w[j]=ws[tid*WSP+j];
    float bi=__ldg(&kp_b2[base+tid]);
    float* gp=g_params+(size_t)b0*P24K+base+tid;
    #pragma unroll 4
    for(int b=0;b<16;++b){
        const float* hb=hs+b*CR;
        float s=bi;
        #pragma unroll
        for(int j=0;j<CR;++j) s+=hb[j]*w[j];
        gp[(size_t)b*P24K]=s;
    }
}

// ---------------- k2c: per-batch stats (u, inv_sigma) ----------------
__global__ void __launch_bounds__(256) params_stats_kernel(){
    int b=blockIdx.x,tid=threadIdx.x;
    const float4* gp=reinterpret_cast<const float4*>(g_params+(size_t)b*P24K);
    float s1=0.f,s2=0.f;
    #pragma unroll
    for(int it=0;it<24;++it){
        float4 v=gp[tid+it*256];
        s1+=v.x+v.y+v.z+v.w;
        s2+=v.x*v.x+v.y*v.y+v.z*v.z+v.w*v.w;
    }
    #pragma unroll
    for(int o=16;o>0;o>>=1){
        s1+=__shfl_down_sync(0xffffffffu,s1,o);
        s2+=__shfl_down_sync(0xffffffffu,s2,o);
    }
    __shared__ float r1[8],r2[8];
    if((tid&31)==0){ r1[tid>>5]=s1; r2[tid>>5]=s2; }
    __syncthreads();
    if(tid==0){
        float a=0.f,q=0.f;
        #pragma unroll
        for(int g=0;g<8;++g){a+=r1[g]; q+=r2[g];}
        float u=a*(1.0f/P24K);
        float var=q*(1.0f/P24K)-u*u;
        g_stats[b]=make_float2(u,rsqrtf(var+1e-12f));
    }
}

// ---------------- k3: circular conv + PE(featnorm inline) + bias -> bf16 y ------------
// 128 threads, 8 outputs/thread (rows h0+4k)
__global__ void __launch_bounds__(128) conv_kernel(const float* __restrict__ x,
                                                   const float* __restrict__ bias,
                                                   const float* __restrict__ fn_std,
                                                   const float* __restrict__ fn_mean){
    __shared__ float tile[32*33];
    __shared__ float pe_s[32];
    int tid=threadIdx.x,bc=blockIdx.x;
    int b=bc/CC,ch=bc%CC;
    const float* pb=g_params+(size_t)b*P24K;
    float2 st=g_stats[b];
    float u=st.x,inv=st.y;
    bool modeH=(ch<C2);
    int kidx=modeH?((2*C2+ch)*32):((3*C2+(ch-C2))*32);
    int pidx=modeH?(ch*32):((C2+(ch-C2))*32);
    int lane=tid&31,h0=tid>>5;     // h0 in 0..3
    if(tid<32){
        float raw=pb[pidx+tid];
        pe_s[tid]=(raw-u)*inv*__ldg(&fn_std[pidx+tid])+__ldg(&fn_mean[pidx+tid]);
    }
    float kraw=__ldg(&pb[kidx+lane]);
    float kv=(kraw-u)*inv*__ldg(&fn_std[kidx+lane])+__ldg(&fn_mean[kidx+lane]);
    __syncthreads();
    const float* xb=x+(size_t)bc*HW;
    #pragma unroll
    for(int r=0;r<8;++r){
        int idx=tid+r*128,g=idx>>5,w=idx&31;
        tile[g*33+w]=xb[idx]+(modeH?pe_s[g]:pe_s[w]);
    }
    __syncthreads();
    float bi=__ldg(&bias[ch]);
    float a[8];
    #pragma unroll
    for(int k=0;k<8;++k) a[k]=0.f;
    float krot[32];
    if(modeH){
        #pragma unroll
        for(int g=0;g<32;++g) krot[g]=__shfl_sync(0xffffffffu,kv,(g-h0)&31);
        #pragma unroll
        for(int g=0;g<32;++g){
            float tv=tile[g*33+lane];
            #pragma unroll
            for(int k=0;k<8;++k) a[k]+=krot[(g-4*k)&31]*tv;
        }
    }else{
        #pragma unroll
        for(int v=0;v<32;++v) krot[v]=__shfl_sync(0xffffffffu,kv,(v-lane)&31);
        #pragma unroll
        for(int v=0;v<32;++v){
            float kvv=krot[v];
            #pragma unroll
            for(int k=0;k<8;++k) a[k]+=kvv*tile[(h0+4*k)*33+v];
        }
    }
    __nv_bfloat16* yo=g_y+(size_t)bc*HW;
    #pragma unroll
    for(int k=0;k<8;++k)
        yo[(h0+4*k)*32+lane]=__float2bfloat16(a[k]+bi);
}

// ---------------- k4: channel LN (bf16 in) -> token-major bf16, vectorized writes -----
#define SMP 392
__global__ void __launch_bounds__(256) ln_kernel(const float* __restrict__ ln_w,
                                                 const float* __restrict__ ln_b){
    int tid=threadIdx.x;
    int tok0=blockIdx.x*32;
    int b=tok0>>10,hw0=tok0&1023;
    int j=tid&31,cg=tid>>5;
    const __nv_bfloat16* yb=g_y+(size_t)b*CC*HW+hw0+j;
    float vals[48],s1=0.f,s2=0.f;
    #pragma unroll
    for(int i=0;i<48;++i){
        int c=cg+i*8;
        float v=__bfloat162float(yb[(size_t)c*HW]);
        vals[i]=v; s1+=v; s2+=v*v;
    }
    __shared__ float rs1[8][32],rs2[8][32],muS[32],rstdS[32];
    rs1[cg][j]=s1; rs2[cg][j]=s2;
    __syncthreads();
    if(tid<32){
        float a=0.f,q=0.f;
        #pragma unroll
        for(int g=0;g<8;++g){a+=rs1[g][tid]; q+=rs2[g][tid];}
        float mu=a*(1.0f/CC);
        float var=q*(1.0f/CC)-mu*mu;
        muS[tid]=mu; rstdS[tid]=rsqrtf(var+1e-6f);
    }
    __syncthreads();
    __shared__ __align__(16) __nv_bfloat16 smo[32*SMP];
    float mu=muS[j],rsd=rstdS[j];
    #pragma unroll
    for(int i=0;i<48;++i){
        int c=cg+i*8;
        float t=(vals[i]-mu)*rsd*ln_w[c]+ln_b[c];
        smo[j*SMP+c]=__float2bfloat16(t);
    }
    __syncthreads();
    uint4* ao=reinterpret_cast<uint4*>(g_aln+(size_t)tok0*CC);
    const uint4* so=reinterpret_cast<const uint4*>(smo);
    #pragma unroll
    for(int it=0;it<6;++it){
        int idx=tid+it*256;
        int jj=idx/48,r8=idx-jj*48;
        ao[jj*48+r8]=so[jj*(SMP/8)+r8];
    }
}

// ---------------- bf16 GEMM mainloop: 128x128xK, BK=32, NS=4 stages ----------------
template<int KDIM>
__device__ __forceinline__ void gemm_tile(const __nv_bfloat16* __restrict__ A,
                                          const __nv_bfloat16* __restrict__ W,
                                          int mBase,int nBase,float acc[2][8][4],
                                          __nv_bfloat16* As,__nv_bfloat16* Ws){
    const int tid=threadIdx.x;
    const int lane=tid&31,warp=tid>>5;
    const int wm=(warp&3)*32,wn=(warp>>2)*64;
    constexpr int KT=KDIM/32;

    auto load_stage=[&](int s,int kt){
        int k0=kt*32;
        __nv_bfloat16* as=As+s*(128*KPAD);
        __nv_bfloat16* ws=Ws+s*(128*KPAD);
        #pragma unroll
        for(int i=tid;i<512;i+=256){
            int row=i>>2,seg=(i&3)*8;
            cp16(as+row*KPAD+seg,A+(size_t)(mBase+row)*KDIM+k0+seg);
            cp16(ws+row*KPAD+seg,W+(size_t)(nBase+row)*KDIM+k0+seg);
        }
        cp_commit();
    };

    load_stage(0,0); load_stage(1,1); load_stage(2,2);

    for(int kt=0;kt<KT;++kt){
        int s=kt&(NS-1);
        cp_wait<NS-2>();
        __syncthreads();
        if(kt+NS-1<KT) load_stage((kt+NS-1)&(NS-1),kt+NS-1);
        else           cp_commit();
        __nv_bfloat16* as=As+s*(128*KPAD);
        __nv_bfloat16* ws=Ws+s*(128*KPAD);
        #pragma unroll
        for(int kk=0;kk<2;++kk){
            unsigned a[2][4],bq[4][4];
            #pragma unroll
            for(int mi=0;mi<2;++mi)
                ldm_x4(smem_u32(as+(wm+mi*16+(lane&15))*KPAD+kk*16+(lane>>4)*8),
                       a[mi][0],a[mi][1],a[mi][2],a[mi][3]);
            #pragma unroll
            for(int nq=0;nq<4;++nq)
                ldm_x4(smem_u32(ws+(wn+nq*16+(lane&15))*KPAD+kk*16+(lane>>4)*8),
                       bq[nq][0],bq[nq][1],bq[nq][2],bq[nq][3]);
            #pragma unroll
            for(int mi=0;mi<2;++mi)
                #pragma unroll
                for(int ni=0;ni<8;++ni){
                    int nq=ni>>1,hp=ni&1;
                    mma16816(acc[mi][ni],a[mi][0],a[mi][1],a[mi][2],a[mi][3],
                             bq[nq][hp],bq[nq][2+hp]);
                }
        }
    }
}

// ---------------- k5: GEMM1 + bias + GELU(tanh) -> g_hid ----------------
__global__ void __launch_bounds__(256) gemm1_kernel(const float* __restrict__ b1){
    extern __shared__ __align__(16) __nv_bfloat16 sm[];
    __nv_bfloat16* As=sm;
    __nv_bfloat16* Ws=sm+NS*128*KPAD;
    float acc[2][8][4];
    #pragma unroll
    for(int i=0;i<2;++i)
        #pragma unroll
        for(int j=0;j<8;++j)
            #pragma unroll
            for(int k=0;k<4;++k) acc[i][j][k]=0.f;

    int mBase=blockIdx.y*128,nBase=blockIdx.x*128;
    gemm_tile<CC>(g_aln,g_w1b,mBase,nBase,acc,As,Ws);

    int lane=threadIdx.x&31,warp=threadIdx.x>>5;
    int wm=mBase+(warp&3)*32,wn=nBase+(warp>>2)*64;
    #pragma unroll
    for(int mi=0;mi<2;++mi)
        #pragma unroll
        for(int ni=0;ni<8;++ni){
            int n=wn+ni*8+(lane&3)*2;
            float bn0=__ldg(&b1[n]),bn1=__ldg(&b1[n+1]);
            int m=wm+mi*16+(lane>>2);
            float c0=gelu_t(acc[mi][ni][0]+bn0);
            float c1=gelu_t(acc[mi][ni][1]+bn1);
            float c2=gelu_t(acc[mi][ni][2]+bn0);
            float c3=gelu_t(acc[mi][ni][3]+bn1);
            *reinterpret_cast<__nv_bfloat162*>(&g_hid[(size_t)m*HID+n])=__floats2bfloat162_rn(c0,c1);
            *reinterpret_cast<__nv_bfloat162*>(&g_hid[(size_t)(m+8)*HID+n])=__floats2bfloat162_rn(c2,c3);
        }
}

// ---------------- k6: GEMM2 + bias + gamma*t + residual -> out ----------------
__global__ void __launch_bounds__(256) gemm2_kernel(const float* __restrict__ x,
                                                    const float* __restrict__ b2,
                                                    const float* __restrict__ gamma,
                                                    float* __restrict__ out){
    extern __shared__ __align__(16) __nv_bfloat16 sm[];
    __nv_bfloat16* As=sm;
    __nv_bfloat16* Ws=sm+NS*128*KPAD;
    float acc[2][8][4];
    #pragma unroll
    for(int i=0;i<2;++i)
        #pragma unroll
        for(int j=0;j<8;++j)
            #pragma unroll
            for(int k=0;k<4;++k) acc[i][j][k]=0.f;

    int mBase=blockIdx.y*128,nBase=blockIdx.x*128;
    gemm_tile<HID>(g_hid,g_w2b,mBase,nBase,acc,As,Ws);

    int lane=threadIdx.x&31,warp=threadIdx.x>>5;
    int wm=mBase+(warp&3)*32,wn=nBase+(warp>>2)*64;
    #pragma unroll
    for(int mi=0;mi<2;++mi)
        #pragma unroll
        for(int ni=0;ni<8;++ni){
            int n=wn+ni*8+(lane&3)*2;
            float bb0=__ldg(&b2[n]),bb1=__ldg(&b2[n+1]);
            float gm0=__ldg(&gamma[n]),gm1=__ldg(&gamma[n+1]);
            int m0=wm+mi*16+(lane>>2);
            #pragma unroll
            for(int half=0;half<2;++half){
                int m=m0+half*8;
                float v0=acc[mi][ni][half*2+0]+bb0;
                float v1=acc[mi][ni][half*2+1]+bb1;
                int b=m>>10,hw=m&1023;
                size_t i0=((size_t)(b*CC+n)<<10)+hw;
                out[i0]     =x[i0]     +gm0*v0;
                out[i0+1024]=x[i0+1024]+gm1*v1;
            }
        }
}

// ---------------- launch ----------------
extern "C" void kernel_launch(void* const* d_in, const int* in_sizes, int n_in,
                              void* d_out, int out_size) {
    const float* x       = (const float*)d_in[0];
    const float* kp_w1   = (const float*)d_in[1];
    const float* bng     = (const float*)d_in[2];
    const float* bnb     = (const float*)d_in[3];
    const float* bnm     = (const float*)d_in[4];
    const float* bnv     = (const float*)d_in[5];
    const float* kp_w2   = (const float*)d_in[6];
    const float* kp_b2   = (const float*)d_in[7];
    const float* fn_std  = (const float*)d_in[8];
    const float* fn_mean = (const float*)d_in[9];
    const float* bias    = (const float*)d_in[10];
    const float* ln_w    = (const float*)d_in[11];
    const float* ln_b    = (const float*)d_in[12];
    const float* w1      = (const float*)d_in[13];
    const float* b1      = (const float*)d_in[14];
    const float* w2      = (const float*)d_in[15];
    const float* b2      = (const float*)d_in[16];
    const float* gamma   = (const float*)d_in[17];
    float* out = (float*)d_out;

    static bool attr_set=false;
    if(!attr_set){
        cudaFuncSetAttribute(gemm1_kernel,cudaFuncAttributeMaxDynamicSharedMemorySize,GEMM_SMEM);
        cudaFuncSetAttribute(gemm2_kernel,cudaFuncAttributeMaxDynamicSharedMemorySize,GEMM_SMEM);
        attr_set=true;
    }

    cvt_w_kernel<<<(HID*CC+255)/256,256>>>(w1,w2);
    pool_kernel<<<BB*CC,256>>>(x);
    params_h_kernel<<<BB,32>>>(kp_w1,bng,bnb,bnm,bnv);
    params_gemm_kernel<<<dim3(P24K/256,4),256>>>(kp_w2,kp_b2);
    params_stats_kernel<<<BB,256>>>();
    conv_kernel<<<BB*CC,128>>>(x,bias,fn_std,fn_mean);
    ln_kernel<<<NTOK/32,256>>>(ln_w,ln_b);
    gemm1_kernel<<<dim3(HID/128,NTOK/128),256,GEMM_SMEM>>>(b1);
    gemm2_kernel<<<dim3(CC/128,NTOK/128),256,GEMM_SMEM>>>(x,b2,gamma,out);
}

// round 17
// speedup vs baseline: 1.0425x; 1.0240x over previous
#include <cuda_runtime.h>
#include <cuda_bf16.h>
#include <cstdint>

#define BB 64
#define CC 384
#define C2 192
#define HW 1024
#define CR 24
#define P24K 24576
#define NTOK 65536
#define HID 1536
#define KPAD 40
#define NS 4
#define GEMM_SMEM (NS*128*KPAD*2*2)   // 81920 B

__device__ float          g_p[BB*CC];
__device__ float          g_h[BB*CR];
__device__ float2         g_stats[BB];
__device__ float          g_params[BB*P24K];         // RAW dyn params
__device__ __nv_bfloat16  g_y[(size_t)BB*CC*HW];
__device__ __nv_bfloat16  g_aln[(size_t)NTOK*CC];
__device__ __nv_bfloat16  g_hid[(size_t)NTOK*HID];
__device__ __nv_bfloat16  g_w1b[HID*CC];
__device__ __nv_bfloat16  g_w2b[CC*HID];

__device__ __forceinline__ unsigned smem_u32(const void* p){return (unsigned)__cvta_generic_to_shared(p);}
__device__ __forceinline__ void cp16(void* s,const void* g){
    asm volatile("cp.async.cg.shared.global [%0], [%1], 16;\n"::"r"(smem_u32(s)),"l"(g));}
__device__ __forceinline__ void cp_commit(){asm volatile("cp.async.commit_group;\n");}
template<int N> __device__ __forceinline__ void cp_wait(){asm volatile("cp.async.wait_group %0;\n"::"n"(N));}
__device__ __forceinline__ void ldm_x4(unsigned addr,unsigned&r0,unsigned&r1,unsigned&r2,unsigned&r3){
    asm volatile("ldmatrix.sync.aligned.m8n8.x4.shared.b16 {%0,%1,%2,%3}, [%4];\n"
                 :"=r"(r0),"=r"(r1),"=r"(r2),"=r"(r3):"r"(addr));}
__device__ __forceinline__ void mma16816(float* c,unsigned a0,unsigned a1,unsigned a2,unsigned a3,
                                         unsigned b0,unsigned b1){
    asm volatile(
        "mma.sync.aligned.m16n8k16.row.col.f32.bf16.bf16.f32 "
        "{%0,%1,%2,%3},{%4,%5,%6,%7},{%8,%9},{%0,%1,%2,%3};\n"
        :"+f"(c[0]),"+f"(c[1]),"+f"(c[2]),"+f"(c[3])
        :"r"(a0),"r"(a1),"r"(a2),"r"(a3),"r"(b0),"r"(b1));}
__device__ __forceinline__ float gelu_t(float v){
    float u=v*(0.7978845608028654f+0.0356774081f*v*v);
    float t; asm("tanh.approx.f32 %0, %1;":"=f"(t):"f"(u));
    return 0.5f*v*(1.0f+t);}

// ---------------- k0: weights -> bf16 ----------------
__global__ void __launch_bounds__(256) cvt_w_kernel(const float* __restrict__ w1,
                                                    const float* __restrict__ w2){
    int i=blockIdx.x*256+threadIdx.x;
    if(i<HID*CC){
        g_w1b[i]=__float2bfloat16(w1[i]);
        g_w2b[i]=__float2bfloat16(w2[i]);
    }
}

// ---------------- k1: spatial mean pool ----------------
__global__ void __launch_bounds__(256) pool_kernel(const float* __restrict__ x){
    const float4* xr=reinterpret_cast<const float4*>(x+(size_t)blockIdx.x*HW);
    float4 v=xr[threadIdx.x];
    float s=v.x+v.y+v.z+v.w;
    #pragma unroll
    for(int o=16;o>0;o>>=1) s+=__shfl_down_sync(0xffffffffu,s,o);
    __shared__ float ws[8];
    if((threadIdx.x&31)==0) ws[threadIdx.x>>5]=s;
    __syncthreads();
    if(threadIdx.x<8){
        float t=ws[threadIdx.x];
        #pragma unroll
        for(int o=4;o>0;o>>=1) t+=__shfl_down_sync(0xffu,t,o);
        if(threadIdx.x==0) g_p[blockIdx.x]=t*(1.0f/1024.0f);
    }
}

// ---------------- k2a: h = relu(bn(p @ kp_w1^T)) ----------------
__global__ void __launch_bounds__(32) params_h_kernel(
    const float* __restrict__ kp_w1,const float* __restrict__ bng,const float* __restrict__ bnb,
    const float* __restrict__ bnm,const float* __restrict__ bnv){
    int b=blockIdx.x,tid=threadIdx.x;
    if(tid<CR){
        const float* p=g_p+b*CC;
        const float* wr=kp_w1+tid*CC;
        float s=0.f;
        #pragma unroll 8
        for(int c=0;c<CC;++c) s+=p[c]*wr[c];
        s=(s-bnm[tid])*rsqrtf(bnv[tid]+1e-5f)*bng[tid]+bnb[tid];
        g_h[b*CR+tid]=fmaxf(s,0.0f);
    }
}

// ---------------- k2b: raw params GEMM, grid (96,4): 256 rows x 16 batches ----------
#define WSP 25
__global__ void __launch_bounds__(256) params_gemm_kernel(
    const float* __restrict__ kp_w2,const float* __restrict__ kp_b2){
    __shared__ float hs[16*CR];
    __shared__ float ws[256*WSP];
    int tid=threadIdx.x;
    int base=blockIdx.x*256;
    int b0=blockIdx.y*16;
    for(int i=tid;i<16*CR;i+=256) hs[i]=g_h[b0*CR+i];
    const float* wsrc=kp_w2+(size_t)base*CR;
    for(int i=tid;i<256*CR;i+=256){
        int r=i/CR,c=i-r*CR;
        ws[r*WSP+c]=wsrc[i];
    }
    __syncthreads();
    float w[CR];
    #pragma unroll
    for(int j=0;j<CR;++j) w[j]=ws[tid*WSP+j];
    float bi=__ldg(&kp_b2[base+tid]);
    float* gp=g_params+(size_t)b0*P24K+base+tid;
    #pragma unroll 4
    for(int b=0;b<16;++b){
        const float* hb=hs+b*CR;
        float s=bi;
        #pragma unroll
        for(int j=0;j<CR;++j) s+=hb[j]*w[j];
        gp[(size_t)b*P24K]=s;
    }
}

// ---------------- k2c: per-batch stats (u, inv_sigma) ----------------
__global__ void __launch_bounds__(256) params_stats_kernel(){
    int b=blockIdx.x,tid=threadIdx.x;
    const float4* gp=reinterpret_cast<const float4*>(g_params+(size_t)b*P24K);
    float s1=0.f,s2=0.f;
    #pragma unroll
    for(int it=0;it<24;++it){
        float4 v=gp[tid+it*256];
        s1+=v.x+v.y+v.z+v.w;
        s2+=v.x*v.x+v.y*v.y+v.z*v.z+v.w*v.w;
    }
    #pragma unroll
    for(int o=16;o>0;o>>=1){
        s1+=__shfl_down_sync(0xffffffffu,s1,o);
        s2+=__shfl_down_sync(0xffffffffu,s2,o);
    }
    __shared__ float r1[8],r2[8];
    if((tid&31)==0){ r1[tid>>5]=s1; r2[tid>>5]=s2; }
    __syncthreads();
    if(tid==0){
        float a=0.f,q=0.f;
        #pragma unroll
        for(int g=0;g<8;++g){a+=r1[g]; q+=r2[g];}
        float u=a*(1.0f/P24K);
        float var=q*(1.0f/P24K)-u*u;
        g_stats[b]=make_float2(u,rsqrtf(var+1e-12f));
    }
}

// ---------------- k3: circular conv + PE(featnorm inline) + bias -> bf16 y ------------
// 128 threads, 8 outputs/thread, packed fma.rn.f32x2 inner loops
__global__ void __launch_bounds__(128) conv_kernel(const float* __restrict__ x,
                                                   const float* __restrict__ bias,
                                                   const float* __restrict__ fn_std,
                                                   const float* __restrict__ fn_mean){
    __shared__ __align__(16) float tile[32*34];
    __shared__ float pe_s[32];
    int tid=threadIdx.x,bc=blockIdx.x;
    int b=bc/CC,ch=bc%CC;
    const float* pb=g_params+(size_t)b*P24K;
    float2 st=g_stats[b];
    float u=st.x,inv=st.y;
    bool modeH=(ch<C2);
    int kidx=modeH?((2*C2+ch)*32):((3*C2+(ch-C2))*32);
    int pidx=modeH?(ch*32):((C2+(ch-C2))*32);
    int lane=tid&31,h0=tid>>5;     // h0 in 0..3
    if(tid<32){
        float raw=pb[pidx+tid];
        pe_s[tid]=(raw-u)*inv*__ldg(&fn_std[pidx+tid])+__ldg(&fn_mean[pidx+tid]);
    }
    float kraw=__ldg(&pb[kidx+lane]);
    float kv=(kraw-u)*inv*__ldg(&fn_std[kidx+lane])+__ldg(&fn_mean[kidx+lane]);
    __syncthreads();
    const float* xb=x+(size_t)bc*HW;
    float bi=__ldg(&bias[ch]);
    __nv_bfloat16* yo=g_y+(size_t)bc*HW;

    if(modeH){
        // tile row-major, stride 33
        #pragma unroll
        for(int r=0;r<8;++r){
            int idx=tid+r*128,g=idx>>5,w=idx&31;
            tile[g*33+w]=xb[idx]+pe_s[g];
        }
        // kp[j] = (krot[j], krot[(j-4)&31]); krot[j]=shfl(kv,(j-h0)&31)
        unsigned long long kp[32];
        #pragma unroll
        for(int j=0;j<32;++j){
            float lo=__shfl_sync(0xffffffffu,kv,(j-h0)&31);
            float hi=__shfl_sync(0xffffffffu,kv,(j-4-h0)&31);
            asm("mov.b64 %0,{%1,%2};":"=l"(kp[j]):"f"(lo),"f"(hi));
        }
        __syncthreads();
        unsigned long long acc2[4]={0ull,0ull,0ull,0ull};
        #pragma unroll
        for(int g=0;g<32;++g){
            float tv=tile[g*33+lane];
            unsigned long long tv2;
            asm("mov.b64 %0,{%1,%1};":"=l"(tv2):"f"(tv));
            asm("fma.rn.f32x2 %0,%1,%2,%0;":"+l"(acc2[0]):"l"(kp[g]),"l"(tv2));
            asm("fma.rn.f32x2 %0,%1,%2,%0;":"+l"(acc2[1]):"l"(kp[(g-8)&31]),"l"(tv2));
            asm("fma.rn.f32x2 %0,%1,%2,%0;":"+l"(acc2[2]):"l"(kp[(g-16)&31]),"l"(tv2));
            asm("fma.rn.f32x2 %0,%1,%2,%0;":"+l"(acc2[3]):"l"(kp[(g-24)&31]),"l"(tv2));
        }
        // pair t: rows (h0+8t, h0+8t+4)
        #pragma unroll
        for(int t=0;t<4;++t){
            float lo,hi;
            asm("mov.b64 {%0,%1},%2;":"=f"(lo),"=f"(hi):"l"(acc2[t]));
            yo[(h0+8*t)*32+lane]  =__float2bfloat16(lo+bi);
            yo[(h0+8*t+4)*32+lane]=__float2bfloat16(hi+bi);
        }
    }else{
        // tile transposed: tile[v*34 + g]  (even stride for LDS.64)
        #pragma unroll
        for(int r=0;r<8;++r){
            int idx=tid+r*128,g=idx>>5,w=idx&31;
            tile[w*34+g]=xb[idx]+pe_s[w];
        }
        float krot[32];
        #pragma unroll
        for(int v=0;v<32;++v) krot[v]=__shfl_sync(0xffffffffu,kv,(v-lane)&31);
        __syncthreads();
        unsigned long long acc2[4]={0ull,0ull,0ull,0ull};
        int r0=2*h0;   // pair t covers rows (r0+8t, r0+8t+1)
        #pragma unroll
        for(int v=0;v<32;++v){
            unsigned long long kv2;
            asm("mov.b64 %0,{%1,%1};":"=l"(kv2):"f"(krot[v]));
            const unsigned long long* tp=
                reinterpret_cast<const unsigned long long*>(&tile[v*34+r0]);
            asm("fma.rn.f32x2 %0,%1,%2,%0;":"+l"(acc2[0]):"l"(kv2),"l"(tp[0]));
            asm("fma.rn.f32x2 %0,%1,%2,%0;":"+l"(acc2[1]):"l"(kv2),"l"(tp[4]));
            asm("fma.rn.f32x2 %0,%1,%2,%0;":"+l"(acc2[2]):"l"(kv2),"l"(tp[8]));
            asm("fma.rn.f32x2 %0,%1,%2,%0;":"+l"(acc2[3]):"l"(kv2),"l"(tp[12]));
        }
        #pragma unroll
        for(int t=0;t<4;++t){
            float lo,hi;
            asm("mov.b64 {%0,%1},%2;":"=f"(lo),"=f"(hi):"l"(acc2[t]));
            yo[(r0+8*t)*32+lane]  =__float2bfloat16(lo+bi);
            yo[(r0+8*t+1)*32+lane]=__float2bfloat16(hi+bi);
        }
    }
}

// ---------------- k4: channel LN (bf16 in) -> token-major bf16, vectorized writes -----
#define SMP 392
__global__ void __launch_bounds__(256) ln_kernel(const float* __restrict__ ln_w,
                                                 const float* __restrict__ ln_b){
    int tid=threadIdx.x;
    int tok0=blockIdx.x*32;
    int b=tok0>>10,hw0=tok0&1023;
    int j=tid&31,cg=tid>>5;
    const __nv_bfloat16* yb=g_y+(size_t)b*CC*HW+hw0+j;
    float vals[48],s1=0.f,s2=0.f;
    #pragma unroll
    for(int i=0;i<48;++i){
        int c=cg+i*8;
        float v=__bfloat162float(yb[(size_t)c*HW]);
        vals[i]=v; s1+=v; s2+=v*v;
    }
    __shared__ float rs1[8][32],rs2[8][32],muS[32],rstdS[32];
    rs1[cg][j]=s1; rs2[cg][j]=s2;
    __syncthreads();
    if(tid<32){
        float a=0.f,q=0.f;
        #pragma unroll
        for(int g=0;g<8;++g){a+=rs1[g][tid]; q+=rs2[g][tid];}
        float mu=a*(1.0f/CC);
        float var=q*(1.0f/CC)-mu*mu;
        muS[tid]=mu; rstdS[tid]=rsqrtf(var+1e-6f);
    }
    __syncthreads();
    __shared__ __align__(16) __nv_bfloat16 smo[32*SMP];
    float mu=muS[j],rsd=rstdS[j];
    #pragma unroll
    for(int i=0;i<48;++i){
        int c=cg+i*8;
        float t=(vals[i]-mu)*rsd*ln_w[c]+ln_b[c];
        smo[j*SMP+c]=__float2bfloat16(t);
    }
    __syncthreads();
    uint4* ao=reinterpret_cast<uint4*>(g_aln+(size_t)tok0*CC);
    const uint4* so=reinterpret_cast<const uint4*>(smo);
    #pragma unroll
    for(int it=0;it<6;++it){
        int idx=tid+it*256;
        int jj=idx/48,r8=idx-jj*48;
        ao[jj*48+r8]=so[jj*(SMP/8)+r8];
    }
}

// ---------------- bf16 GEMM mainloop: 128x128xK, BK=32, NS=4 stages ----------------
template<int KDIM>
__device__ __forceinline__ void gemm_tile(const __nv_bfloat16* __restrict__ A,
                                          const __nv_bfloat16* __restrict__ W,
                                          int mBase,int nBase,float acc[2][8][4],
                                          __nv_bfloat16* As,__nv_bfloat16* Ws){
    const int tid=threadIdx.x;
    const int lane=tid&31,warp=tid>>5;
    const int wm=(warp&3)*32,wn=(warp>>2)*64;
    constexpr int KT=KDIM/32;

    auto load_stage=[&](int s,int kt){
        int k0=kt*32;
        __nv_bfloat16* as=As+s*(128*KPAD);
        __nv_bfloat16* ws=Ws+s*(128*KPAD);
        #pragma unroll
        for(int i=tid;i<512;i+=256){
            int row=i>>2,seg=(i&3)*8;
            cp16(as+row*KPAD+seg,A+(size_t)(mBase+row)*KDIM+k0+seg);
            cp16(ws+row*KPAD+seg,W+(size_t)(nBase+row)*KDIM+k0+seg);
        }
        cp_commit();
    };

    load_stage(0,0); load_stage(1,1); load_stage(2,2);

    for(int kt=0;kt<KT;++kt){
        int s=kt&(NS-1);
        cp_wait<NS-2>();
        __syncthreads();
        if(kt+NS-1<KT) load_stage((kt+NS-1)&(NS-1),kt+NS-1);
        else           cp_commit();
        __nv_bfloat16* as=As+s*(128*KPAD);
        __nv_bfloat16* ws=Ws+s*(128*KPAD);
        #pragma unroll
        for(int kk=0;kk<2;++kk){
            unsigned a[2][4],bq[4][4];
            #pragma unroll
            for(int mi=0;mi<2;++mi)
                ldm_x4(smem_u32(as+(wm+mi*16+(lane&15))*KPAD+kk*16+(lane>>4)*8),
                       a[mi][0],a[mi][1],a[mi][2],a[mi][3]);
            #pragma unroll
            for(int nq=0;nq<4;++nq)
                ldm_x4(smem_u32(ws+(wn+nq*16+(lane&15))*KPAD+kk*16+(lane>>4)*8),
                       bq[nq][0],bq[nq][1],bq[nq][2],bq[nq][3]);
            #pragma unroll
            for(int mi=0;mi<2;++mi)
                #pragma unroll
                for(int ni=0;ni<8;++ni){
                    int nq=ni>>1,hp=ni&1;
                    mma16816(acc[mi][ni],a[mi][0],a[mi][1],a[mi][2],a[mi][3],
                             bq[nq][hp],bq[nq][2+hp]);
                }
        }
    }
}

// ---------------- k5: GEMM1 + bias + GELU(tanh) -> g_hid ----------------
__global__ void __launch_bounds__(256) gemm1_kernel(const float* __restrict__ b1){
    extern __shared__ __align__(16) __nv_bfloat16 sm[];
    __nv_bfloat16* As=sm;
    __nv_bfloat16* Ws=sm+NS*128*KPAD;
    float acc[2][8][4];
    #pragma unroll
    for(int i=0;i<2;++i)
        #pragma unroll
        for(int j=0;j<8;++j)
            #pragma unroll
            for(int k=0;k<4;++k) acc[i][j][k]=0.f;

    int mBase=blockIdx.y*128,nBase=blockIdx.x*128;
    gemm_tile<CC>(g_aln,g_w1b,mBase,nBase,acc,As,Ws);

    int lane=threadIdx.x&31,warp=threadIdx.x>>5;
    int wm=mBase+(warp&3)*32,wn=nBase+(warp>>2)*64;
    #pragma unroll
    for(int mi=0;mi<2;++mi)
        #pragma unroll
        for(int ni=0;ni<8;++ni){
            int n=wn+ni*8+(lane&3)*2;
            float bn0=__ldg(&b1[n]),bn1=__ldg(&b1[n+1]);
            int m=wm+mi*16+(lane>>2);
            float c0=gelu_t(acc[mi][ni][0]+bn0);
            float c1=gelu_t(acc[mi][ni][1]+bn1);
            float c2=gelu_t(acc[mi][ni][2]+bn0);
            float c3=gelu_t(acc[mi][ni][3]+bn1);
            *reinterpret_cast<__nv_bfloat162*>(&g_hid[(size_t)m*HID+n])=__floats2bfloat162_rn(c0,c1);
            *reinterpret_cast<__nv_bfloat162*>(&g_hid[(size_t)(m+8)*HID+n])=__floats2bfloat162_rn(c2,c3);
        }
}

// ---------------- k6: GEMM2 + bias + gamma*t + residual -> out ----------------
__global__ void __launch_bounds__(256) gemm2_kernel(const float* __restrict__ x,
                                                    const float* __restrict__ b2,
                                                    const float* __restrict__ gamma,
                                                    float* __restrict__ out){
    extern __shared__ __align__(16) __nv_bfloat16 sm[];
    __nv_bfloat16* As=sm;
    __nv_bfloat16* Ws=sm+NS*128*KPAD;
    float acc[2][8][4];
    #pragma unroll
    for(int i=0;i<2;++i)
        #pragma unroll
        for(int j=0;j<8;++j)
            #pragma unroll
            for(int k=0;k<4;++k) acc[i][j][k]=0.f;

    int mBase=blockIdx.y*128,nBase=blockIdx.x*128;
    gemm_tile<HID>(g_hid,g_w2b,mBase,nBase,acc,As,Ws);

    int lane=threadIdx.x&31,warp=threadIdx.x>>5;
    int wm=mBase+(warp&3)*32,wn=nBase+(warp>>2)*64;
    #pragma unroll
    for(int mi=0;mi<2;++mi)
        #pragma unroll
        for(int ni=0;ni<8;++ni){
            int n=wn+ni*8+(lane&3)*2;
            float bb0=__ldg(&b2[n]),bb1=__ldg(&b2[n+1]);
            float gm0=__ldg(&gamma[n]),gm1=__ldg(&gamma[n+1]);
            int m0=wm+mi*16+(lane>>2);
            #pragma unroll
            for(int half=0;half<2;++half){
                int m=m0+half*8;
                float v0=acc[mi][ni][half*2+0]+bb0;
                float v1=acc[mi][ni][half*2+1]+bb1;
                int b=m>>10,hw=m&1023;
                size_t i0=((size_t)(b*CC+n)<<10)+hw;
                out[i0]     =x[i0]     +gm0*v0;
                out[i0+1024]=x[i0+1024]+gm1*v1;
            }
        }
}

// ---------------- launch ----------------
extern "C" void kernel_launch(void* const* d_in, const int* in_sizes, int n_in,
                              void* d_out, int out_size) {
    const float* x       = (const float*)d_in[0];
    const float* kp_w1   = (const float*)d_in[1];
    const float* bng     = (const float*)d_in[2];
    const float* bnb     = (const float*)d_in[3];
    const float* bnm     = (const float*)d_in[4];
    const float* bnv     = (const float*)d_in[5];
    const float* kp_w2   = (const float*)d_in[6];
    const float* kp_b2   = (const float*)d_in[7];
    const float* fn_std  = (const float*)d_in[8];
    const float* fn_mean = (const float*)d_in[9];
    const float* bias    = (const float*)d_in[10];
    const float* ln_w    = (const float*)d_in[11];
    const float* ln_b    = (const float*)d_in[12];
    const float* w1      = (const float*)d_in[13];
    const float* b1      = (const float*)d_in[14];
    const float* w2      = (const float*)d_in[15];
    const float* b2      = (const float*)d_in[16];
    const float* gamma   = (const float*)d_in[17];
    float* out = (float*)d_out;

    static bool attr_set=false;
    if(!attr_set){
        cudaFuncSetAttribute(gemm1_kernel,cudaFuncAttributeMaxDynamicSharedMemorySize,GEMM_SMEM);
        cudaFuncSetAttribute(gemm2_kernel,cudaFuncAttributeMaxDynamicSharedMemorySize,GEMM_SMEM);
        attr_set=true;
    }

    cvt_w_kernel<<<(HID*CC+255)/256,256>>>(w1,w2);
    pool_kernel<<<BB*CC,256>>>(x);
    params_h_kernel<<<BB,32>>>(kp_w1,bng,bnb,bnm,bnv);
    params_gemm_kernel<<<dim3(P24K/256,4),256>>>(kp_w2,kp_b2);
    params_stats_kernel<<<BB,256>>>();
    conv_kernel<<<BB*CC,128>>>(x,bias,fn_std,fn_mean);
    ln_kernel<<<NTOK/32,256>>>(ln_w,ln_b);
    gemm1_kernel<<<dim3(HID/128,NTOK/128),256,GEMM_SMEM>>>(b1);
    gemm2_kernel<<<dim3(CC/128,NTOK/128),256,GEMM_SMEM>>>(x,b2,gamma,out);
}